// round 1
// baseline (speedup 1.0000x reference)
#include <cuda_runtime.h>
#include <math.h>

// Problem constants (B=4, H=W=128, C=256, heads=8, d=32, hid=768)
#define BB 4
#define HH_IMG 128
#define WW_IMG 128
#define NN 16384           // H*W
#define CC 256
#define HID 768
#define NHEAD 8
#define DHEAD 32
#define MROWS (BB*NN)      // 65536

// ---------------- scratch (device globals; no allocation allowed) ------------
__device__ float g_ln [(size_t)MROWS*CC];     // LN output (reused ln1/ln2)
__device__ float g_qkv[(size_t)MROWS*HID];    // qkv projection
__device__ float g_att[(size_t)MROWS*CC];     // attention output (B,N,C)
__device__ float g_x2 [(size_t)MROWS*CC];     // x after attention residual
__device__ float g_hdn[(size_t)MROWS*HID];    // fc1 output
__device__ float g_act[(size_t)MROWS*HID];    // gelu(hdn + dwconv)
__device__ float g_cmax[BB*CC];               // per (b, h*d) column max of k
__device__ float g_csuminv[BB*CC];            // 1/sum(exp(k-max)) per column
__device__ float g_kv[BB*NHEAD*DHEAD*DHEAD];  // kv [b,h,32,32]

// ---------------- LayerNorm: one block (256 thr) per row ---------------------
__global__ void ln_kernel(const float* __restrict__ in, const float* __restrict__ g,
                          const float* __restrict__ b, float* __restrict__ out) {
    int row = blockIdx.x;
    int t = threadIdx.x;
    float v = in[(size_t)row*CC + t];
    __shared__ float red[256];
    red[t] = v; __syncthreads();
    #pragma unroll
    for (int s = 128; s > 0; s >>= 1) { if (t < s) red[t] += red[t+s]; __syncthreads(); }
    float mean = red[0] * (1.0f/CC);
    __syncthreads();
    float dv = v - mean;
    red[t] = dv*dv; __syncthreads();
    #pragma unroll
    for (int s = 128; s > 0; s >>= 1) { if (t < s) red[t] += red[t+s]; __syncthreads(); }
    float var = red[0] * (1.0f/CC);
    out[(size_t)row*CC + t] = dv * rsqrtf(var + 1e-6f) * g[t] + b[t];
}

// ---------------- SGEMM: C[M,N] = A[M,K] @ B[K,N] + bias (+ residual) --------
// 128x128 block tile, BK=16, 256 threads, 8x8 per-thread microtile.
// M % 128 == 0, N % 128 == 0, K % 16 == 0 for all call sites (no guards needed).
template <bool RES>
__global__ __launch_bounds__(256)
void sgemm_kernel(const float* __restrict__ A, const float* __restrict__ Bm,
                  const float* __restrict__ bias, const float* __restrict__ res,
                  float* __restrict__ Cm, int M, int N, int K) {
    const int BM = 128, BN = 128, BK = 16;
    __shared__ float As[BK][BM];
    __shared__ float Bs[BK][BN];
    int tid = threadIdx.x;
    int m0 = blockIdx.y * BM;
    int n0 = blockIdx.x * BN;
    int ty = tid >> 4;       // 0..15 (row group)
    int tx = tid & 15;       // 0..15 (col group)

    float acc[8][8];
    #pragma unroll
    for (int i = 0; i < 8; i++)
        #pragma unroll
        for (int j = 0; j < 8; j++) acc[i][j] = 0.f;

    for (int k0 = 0; k0 < K; k0 += BK) {
        // Load A tile (128 x 16) transposed into As[k][m]; 512 float4, 2/thread
        #pragma unroll
        for (int i = 0; i < 2; i++) {
            int v = tid + i*256;
            int r = v >> 2, kq = v & 3;
            float4 a4 = *(const float4*)(A + (size_t)(m0 + r)*K + k0 + kq*4);
            As[kq*4+0][r] = a4.x; As[kq*4+1][r] = a4.y;
            As[kq*4+2][r] = a4.z; As[kq*4+3][r] = a4.w;
        }
        // Load B tile (16 x 128) straight; 512 float4, 2/thread
        #pragma unroll
        for (int i = 0; i < 2; i++) {
            int v = tid + i*256;
            int kr = v >> 5, nq = v & 31;
            *(float4*)(&Bs[kr][nq*4]) =
                *(const float4*)(Bm + (size_t)(k0 + kr)*N + n0 + nq*4);
        }
        __syncthreads();
        #pragma unroll
        for (int kk = 0; kk < BK; kk++) {
            float a[8], b[8];
            *(float4*)(a)   = *(const float4*)(&As[kk][ty*8]);
            *(float4*)(a+4) = *(const float4*)(&As[kk][ty*8+4]);
            *(float4*)(b)   = *(const float4*)(&Bs[kk][tx*8]);
            *(float4*)(b+4) = *(const float4*)(&Bs[kk][tx*8+4]);
            #pragma unroll
            for (int i = 0; i < 8; i++)
                #pragma unroll
                for (int j = 0; j < 8; j++)
                    acc[i][j] += a[i]*b[j];
        }
        __syncthreads();
    }

    // Epilogue
    #pragma unroll
    for (int i = 0; i < 8; i++) {
        size_t row = (size_t)(m0 + ty*8 + i);
        float* cp = Cm + row*N + n0 + tx*8;
        const float* bp = bias + n0 + tx*8;
        if (RES) {
            const float* rp = res + row*N + n0 + tx*8;
            #pragma unroll
            for (int j = 0; j < 8; j++) cp[j] = acc[i][j] + bp[j] + rp[j];
        } else {
            #pragma unroll
            for (int j = 0; j < 8; j++) cp[j] = acc[i][j] + bp[j];
        }
    }
}

// ---------------- Column softmax stats over tokens (axis N) ------------------
// One block per column (b, c) with c = h*32+d; k lives at qkv[...,256+c], stride HID.
__global__ void colstat_kernel(const float* __restrict__ qkv,
                               float* __restrict__ cmax, float* __restrict__ csuminv) {
    int col = blockIdx.x;            // 0..1023
    int b = col >> 8, c = col & 255;
    const float* base = qkv + (size_t)b*NN*HID + CC + c;
    int t = threadIdx.x;
    __shared__ float red[256];
    float m = -1e30f;
    for (int n = t; n < NN; n += 256) m = fmaxf(m, base[(size_t)n*HID]);
    red[t] = m; __syncthreads();
    #pragma unroll
    for (int s = 128; s > 0; s >>= 1) { if (t < s) red[t] = fmaxf(red[t], red[t+s]); __syncthreads(); }
    m = red[0]; __syncthreads();
    float sm = 0.f;
    for (int n = t; n < NN; n += 256) sm += expf(base[(size_t)n*HID] - m);
    red[t] = sm; __syncthreads();
    #pragma unroll
    for (int s = 128; s > 0; s >>= 1) { if (t < s) red[t] += red[t+s]; __syncthreads(); }
    if (t == 0) { cmax[col] = m; csuminv[col] = 1.0f / red[0]; }
}

__global__ void kv_zero_kernel(float* __restrict__ kv) {
    kv[blockIdx.x*256 + threadIdx.x] = 0.f;
}

// ---------------- kv[b,h,k,v] = sum_n softmax(k)[n,k] * v[n,v] ---------------
// grid (32 bh, 16 n-chunks), 1024 threads; thread owns one (k,v) output.
__global__ __launch_bounds__(1024)
void kv_kernel(const float* __restrict__ qkv, const float* __restrict__ cmax,
               const float* __restrict__ csuminv, float* __restrict__ kvout) {
    int bh = blockIdx.x;
    int b = bh >> 3, hh = bh & 7;
    int t = threadIdx.x;
    int kk = t >> 5, vv = t & 31;
    int cc = t & 31;         // channel lane for loading
    int r0 = t >> 5;         // row lane for loading (0..31)
    __shared__ float ks[64][32];
    __shared__ float vs[64][32];
    int colbase = b*256 + hh*32;
    float mx = cmax[colbase + cc];
    float si = csuminv[colbase + cc];
    size_t nbase = (size_t)b*NN + (size_t)blockIdx.y * 1024;
    float acc = 0.f;
    for (int nt = 0; nt < 1024; nt += 64) {
        #pragma unroll
        for (int j = 0; j < 2; j++) {
            int r = r0 + j*32;
            const float* rowp = qkv + (nbase + nt + r)*HID + hh*32 + cc;
            ks[r][cc] = expf(rowp[CC] - mx) * si;   // softmaxed k
            vs[r][cc] = rowp[2*CC];                 // v
        }
        __syncthreads();
        #pragma unroll
        for (int r = 0; r < 64; r++) acc += ks[r][kk]*vs[r][vv];
        __syncthreads();
    }
    atomicAdd(&kvout[bh*1024 + kk*32 + vv], acc);
}

// ---------------- att = scale * (q@kv) + q * dwconv3x3(v) (head-major) -------
// One block per (b, n), 256 threads = one per channel c = h*32+d.
__global__ void att_kernel(const float* __restrict__ qkv, const float* __restrict__ kv,
                           const float* __restrict__ cw, const float* __restrict__ cb,
                           float* __restrict__ att) {
    int bn = blockIdx.x;
    int b = bn >> 14;
    int n = bn & (NN - 1);
    int y = n >> 7, x = n & 127;
    int c = threadIdx.x;
    int hh = c >> 5, dd = c & 31;
    __shared__ float qs[256];
    float qv = qkv[(size_t)bn*HID + c];
    qs[c] = qv;
    __syncthreads();
    // factor = q @ kv
    float f = 0.f;
    const float* kvp = kv + ((b*8 + hh) << 10) + dd;   // kv[b,hh,k,dd], stride 32
    #pragma unroll
    for (int k = 0; k < 32; k++) f += qs[hh*32 + k] * kvp[k*32];
    // conv_v = depthwise 3x3 of v on the HxW grid (+ bias)
    float cv = cb[c];
    #pragma unroll
    for (int dy = -1; dy <= 1; dy++) {
        int yy = y + dy; if (yy < 0 || yy >= HH_IMG) continue;
        #pragma unroll
        for (int dx = -1; dx <= 1; dx++) {
            int xx = x + dx; if (xx < 0 || xx >= WW_IMG) continue;
            cv += cw[c*9 + (dy+1)*3 + (dx+1)] *
                  qkv[((size_t)b*NN + yy*WW_IMG + xx)*HID + 2*CC + c];
        }
    }
    att[(size_t)bn*CC + c] = 0.17677669529663689f * f + qv * cv;  // 32^-0.5
}

// ---------------- hdn -> gelu(hdn + dwconv3x3(hdn)) (exact GELU) -------------
__global__ void dcgelu_kernel(const float* __restrict__ hdn, const float* __restrict__ w,
                              const float* __restrict__ bias, float* __restrict__ out) {
    int bn = blockIdx.x;
    int b = bn >> 14;
    int n = bn & (NN - 1);
    int y = n >> 7, x = n & 127;
    for (int c = threadIdx.x; c < HID; c += 256) {
        float center = hdn[(size_t)bn*HID + c];
        float acc = bias[c];
        #pragma unroll
        for (int dy = -1; dy <= 1; dy++) {
            int yy = y + dy; if (yy < 0 || yy >= HH_IMG) continue;
            #pragma unroll
            for (int dx = -1; dx <= 1; dx++) {
                int xx = x + dx; if (xx < 0 || xx >= WW_IMG) continue;
                acc += w[c*9 + (dy+1)*3 + (dx+1)] *
                       hdn[((size_t)b*NN + yy*WW_IMG + xx)*HID + c];
            }
        }
        float tsum = center + acc;
        out[(size_t)bn*HID + c] = 0.5f * tsum * (1.0f + erff(tsum * 0.70710678118654752f));
    }
}

// -----------------------------------------------------------------------------
extern "C" void kernel_launch(void* const* d_in, const int* in_sizes, int n_in,
                              void* d_out, int out_size) {
    const float* x       = (const float*)d_in[0];
    // d_in[1]=H, d_in[2]=W (int scalars; shapes hardcoded)
    const float* ln1_g   = (const float*)d_in[3];
    const float* ln1_b   = (const float*)d_in[4];
    const float* qkv_w   = (const float*)d_in[5];
    const float* qkv_b   = (const float*)d_in[6];
    const float* crpe_w  = (const float*)d_in[7];
    const float* crpe_b  = (const float*)d_in[8];
    const float* proj_w  = (const float*)d_in[9];
    const float* proj_b  = (const float*)d_in[10];
    const float* ln2_g   = (const float*)d_in[11];
    const float* ln2_b   = (const float*)d_in[12];
    const float* fc1_w   = (const float*)d_in[13];
    const float* fc1_b   = (const float*)d_in[14];
    const float* dconv_w = (const float*)d_in[15];
    const float* dconv_b = (const float*)d_in[16];
    const float* fc2_w   = (const float*)d_in[17];
    const float* fc2_b   = (const float*)d_in[18];
    float* out = (float*)d_out;

    float *p_ln, *p_qkv, *p_att, *p_x2, *p_hdn, *p_act, *p_cmax, *p_csum, *p_kv;
    cudaGetSymbolAddress((void**)&p_ln,   g_ln);
    cudaGetSymbolAddress((void**)&p_qkv,  g_qkv);
    cudaGetSymbolAddress((void**)&p_att,  g_att);
    cudaGetSymbolAddress((void**)&p_x2,   g_x2);
    cudaGetSymbolAddress((void**)&p_hdn,  g_hdn);
    cudaGetSymbolAddress((void**)&p_act,  g_act);
    cudaGetSymbolAddress((void**)&p_cmax, g_cmax);
    cudaGetSymbolAddress((void**)&p_csum, g_csuminv);
    cudaGetSymbolAddress((void**)&p_kv,   g_kv);

    // --- attention branch ---
    ln_kernel<<<MROWS, 256>>>(x, ln1_g, ln1_b, p_ln);
    sgemm_kernel<false><<<dim3(HID/128, MROWS/128), 256>>>(
        p_ln, qkv_w, qkv_b, nullptr, p_qkv, MROWS, HID, CC);
    colstat_kernel<<<BB*CC, 256>>>(p_qkv, p_cmax, p_csum);
    kv_zero_kernel<<<(BB*NHEAD*DHEAD*DHEAD)/256, 256>>>(p_kv);
    kv_kernel<<<dim3(BB*NHEAD, 16), 1024>>>(p_qkv, p_cmax, p_csum, p_kv);
    att_kernel<<<MROWS, 256>>>(p_qkv, p_kv, crpe_w, crpe_b, p_att);
    sgemm_kernel<true><<<dim3(CC/128, MROWS/128), 256>>>(
        p_att, proj_w, proj_b, x, p_x2, MROWS, CC, CC);

    // --- conv-MLP branch ---
    ln_kernel<<<MROWS, 256>>>(p_x2, ln2_g, ln2_b, p_ln);
    sgemm_kernel<false><<<dim3(HID/128, MROWS/128), 256>>>(
        p_ln, fc1_w, fc1_b, nullptr, p_hdn, MROWS, HID, CC);
    dcgelu_kernel<<<MROWS, 256>>>(p_hdn, dconv_w, dconv_b, p_act);
    sgemm_kernel<true><<<dim3(CC/128, MROWS/128), 256>>>(
        p_act, fc2_w, fc2_b, p_x2, out, MROWS, CC, HID);
}

// round 5
// speedup vs baseline: 1.6611x; 1.6611x over previous
#include <cuda_runtime.h>
#include <math.h>
#include <stdint.h>

// Problem constants (B=4, H=W=128, C=256, heads=8, d=32, hid=768)
#define BB 4
#define HH_IMG 128
#define WW_IMG 128
#define NN 16384           // H*W
#define CC 256
#define HID 768
#define NHEAD 8
#define DHEAD 32
#define MROWS (BB*NN)      // 65536

// ---------------- scratch (device globals; no allocation allowed) ------------
__device__ float g_ln [(size_t)MROWS*CC];     // LN output (reused ln1/ln2)
__device__ float g_qkv[(size_t)MROWS*HID];    // qkv projection
__device__ float g_att[(size_t)MROWS*CC];     // attention output (B,N,C)
__device__ float g_x2 [(size_t)MROWS*CC];     // x after attention residual
__device__ float g_hdn[(size_t)MROWS*HID];    // fc1 output
__device__ float g_act[(size_t)MROWS*HID];    // gelu(hdn + dwconv)
__device__ float g_cmax[BB*CC];
__device__ float g_csuminv[BB*CC];
__device__ float g_kv[BB*NHEAD*DHEAD*DHEAD];

// ---------------- helpers ----------------------------------------------------
__device__ __forceinline__ float to_tf32(float x) {
    float r;
    asm("cvt.rna.tf32.f32 %0, %1;" : "=f"(r) : "f"(x));
    return r;
}
__device__ __forceinline__ void mma_tf32(float c[4], uint32_t a0, uint32_t a1,
                                         uint32_t a2, uint32_t a3,
                                         uint32_t b0, uint32_t b1) {
    asm volatile(
        "mma.sync.aligned.m16n8k8.row.col.f32.tf32.tf32.f32 "
        "{%0,%1,%2,%3}, {%4,%5,%6,%7}, {%8,%9}, {%0,%1,%2,%3};"
        : "+f"(c[0]), "+f"(c[1]), "+f"(c[2]), "+f"(c[3])
        : "r"(a0), "r"(a1), "r"(a2), "r"(a3), "r"(b0), "r"(b1));
}

// ---------------- tensor-core tf32 GEMM: C = A[M,K] @ W[K,N] + bias (+res) ---
// 128x128 CTA tile, BK=32, 256 threads (8 warps, each 64x32), 2 CTAs/SM.
template <bool RES>
__global__ __launch_bounds__(256, 2)
void mma_gemm(const float* __restrict__ A, const float* __restrict__ W,
              const float* __restrict__ bias, const float* __restrict__ res,
              float* __restrict__ Cm, int M, int N, int K) {
    __shared__ float As[32][132];   // [k][m], pad 4 -> conflict-free frag reads
    __shared__ float Bs[32][132];   // [k][n], pad 4 (row stride 528B, 16B-mult)

    const int tid = threadIdx.x;
    const int wid = tid >> 5;
    const int lane = tid & 31;
    const int grp = lane >> 2;      // 0..7
    const int tig = lane & 3;       // 0..3
    const int wy = wid >> 2;        // 0..1  (64-row band)
    const int wx = wid & 3;         // 0..3  (32-col band)
    const int rowbase = wy * 64;
    const int colbase = wx * 32;

    const int m0 = blockIdx.y * 128;
    const int n0 = blockIdx.x * 128;

    float c[4][4][4];
    #pragma unroll
    for (int mt = 0; mt < 4; mt++)
        #pragma unroll
        for (int nt = 0; nt < 4; nt++)
            #pragma unroll
            for (int j = 0; j < 4; j++) c[mt][nt][j] = 0.f;

    const int nkt = K >> 5;
    for (int kt = 0; kt < nkt; kt++) {
        // A tile: 128 rows x 32 k -> As[k][m] (transpose), tf32-rounded
        {
            const float* Ap = A + (size_t)m0 * K + kt * 32;
            #pragma unroll
            for (int i = 0; i < 4; i++) {
                int v = tid + i * 256;
                int r = v >> 3, c8 = v & 7;
                float4 t4 = *(const float4*)(Ap + (size_t)r * K + c8 * 4);
                As[c8*4+0][r] = to_tf32(t4.x);
                As[c8*4+1][r] = to_tf32(t4.y);
                As[c8*4+2][r] = to_tf32(t4.z);
                As[c8*4+3][r] = to_tf32(t4.w);
            }
        }
        // B tile: 32 k-rows x 128 n -> Bs[k][n] (direct), tf32-rounded
        {
            const float* Wp = W + (size_t)(kt * 32) * N + n0;
            #pragma unroll
            for (int i = 0; i < 4; i++) {
                int v = tid + i * 256;
                int kr = v >> 5, nq = v & 31;
                float4 t4 = *(const float4*)(Wp + (size_t)kr * N + nq * 4);
                float4 o;
                o.x = to_tf32(t4.x); o.y = to_tf32(t4.y);
                o.z = to_tf32(t4.z); o.w = to_tf32(t4.w);
                *(float4*)(&Bs[kr][nq*4]) = o;
            }
        }
        __syncthreads();

        #pragma unroll
        for (int ks = 0; ks < 4; ks++) {
            const int kb = ks * 8;
            uint32_t af[4][4];
            #pragma unroll
            for (int mt = 0; mt < 4; mt++) {
                int r = rowbase + mt * 16 + grp;
                af[mt][0] = __float_as_uint(As[kb + tig    ][r    ]);
                af[mt][1] = __float_as_uint(As[kb + tig    ][r + 8]);
                af[mt][2] = __float_as_uint(As[kb + tig + 4][r    ]);
                af[mt][3] = __float_as_uint(As[kb + tig + 4][r + 8]);
            }
            uint32_t bf[4][2];
            #pragma unroll
            for (int nt = 0; nt < 4; nt++) {
                int cn = colbase + nt * 8 + grp;
                bf[nt][0] = __float_as_uint(Bs[kb + tig    ][cn]);
                bf[nt][1] = __float_as_uint(Bs[kb + tig + 4][cn]);
            }
            #pragma unroll
            for (int mt = 0; mt < 4; mt++)
                #pragma unroll
                for (int nt = 0; nt < 4; nt++)
                    mma_tf32(c[mt][nt], af[mt][0], af[mt][1], af[mt][2], af[mt][3],
                             bf[nt][0], bf[nt][1]);
        }
        __syncthreads();
    }

    // epilogue: c0,c1 -> row r, cols 2t,2t+1 ; c2,c3 -> row r+8
    #pragma unroll
    for (int mt = 0; mt < 4; mt++) {
        #pragma unroll
        for (int nt = 0; nt < 4; nt++) {
            int r = m0 + rowbase + mt * 16 + grp;
            int cn = n0 + colbase + nt * 8 + tig * 2;
            #pragma unroll
            for (int half = 0; half < 2; half++) {
                size_t row = (size_t)(r + half * 8);
                size_t off = row * N + cn;
                float2 o;
                o.x = c[mt][nt][half*2 + 0] + bias[cn + 0];
                o.y = c[mt][nt][half*2 + 1] + bias[cn + 1];
                if (RES) {
                    o.x += res[off];
                    o.y += res[off + 1];
                }
                *(float2*)(Cm + off) = o;
            }
        }
    }
}

// ---------------- LayerNorm: one block (256 thr) per row ---------------------
__global__ void ln_kernel(const float* __restrict__ in, const float* __restrict__ g,
                          const float* __restrict__ b, float* __restrict__ out) {
    int row = blockIdx.x;
    int t = threadIdx.x;
    float v = in[(size_t)row*CC + t];
    __shared__ float red[256];
    red[t] = v; __syncthreads();
    #pragma unroll
    for (int s = 128; s > 0; s >>= 1) { if (t < s) red[t] += red[t+s]; __syncthreads(); }
    float mean = red[0] * (1.0f/CC);
    __syncthreads();
    float dv = v - mean;
    red[t] = dv*dv; __syncthreads();
    #pragma unroll
    for (int s = 128; s > 0; s >>= 1) { if (t < s) red[t] += red[t+s]; __syncthreads(); }
    float var = red[0] * (1.0f/CC);
    out[(size_t)row*CC + t] = dv * rsqrtf(var + 1e-6f) * g[t] + b[t];
}

// ---------------- Column softmax stats over tokens (axis N) ------------------
__global__ void colstat_kernel(const float* __restrict__ qkv,
                               float* __restrict__ cmax, float* __restrict__ csuminv) {
    int col = blockIdx.x;            // 0..1023
    int b = col >> 8, c = col & 255;
    const float* base = qkv + (size_t)b*NN*HID + CC + c;
    int t = threadIdx.x;
    __shared__ float red[256];
    float m = -1e30f;
    for (int n = t; n < NN; n += 256) m = fmaxf(m, base[(size_t)n*HID]);
    red[t] = m; __syncthreads();
    #pragma unroll
    for (int s = 128; s > 0; s >>= 1) { if (t < s) red[t] = fmaxf(red[t], red[t+s]); __syncthreads(); }
    m = red[0]; __syncthreads();
    float sm = 0.f;
    for (int n = t; n < NN; n += 256) sm += expf(base[(size_t)n*HID] - m);
    red[t] = sm; __syncthreads();
    #pragma unroll
    for (int s = 128; s > 0; s >>= 1) { if (t < s) red[t] += red[t+s]; __syncthreads(); }
    if (t == 0) { cmax[col] = m; csuminv[col] = 1.0f / red[0]; }
}

__global__ void kv_zero_kernel(float* __restrict__ kv) {
    kv[blockIdx.x*256 + threadIdx.x] = 0.f;
}

// ---------------- kv[b,h,k,v] = sum_n softmax(k)[n,k] * v[n,v] ---------------
__global__ __launch_bounds__(1024)
void kv_kernel(const float* __restrict__ qkv, const float* __restrict__ cmax,
               const float* __restrict__ csuminv, float* __restrict__ kvout) {
    int bh = blockIdx.x;
    int b = bh >> 3, hh = bh & 7;
    int t = threadIdx.x;
    int kk = t >> 5, vv = t & 31;
    int cc = t & 31;
    int r0 = t >> 5;
    __shared__ float ks[64][32];
    __shared__ float vs[64][32];
    int colbase = b*256 + hh*32;
    float mx = cmax[colbase + cc];
    float si = csuminv[colbase + cc];
    size_t nbase = (size_t)b*NN + (size_t)blockIdx.y * 1024;
    float acc = 0.f;
    for (int nt = 0; nt < 1024; nt += 64) {
        #pragma unroll
        for (int j = 0; j < 2; j++) {
            int r = r0 + j*32;
            const float* rowp = qkv + (nbase + nt + r)*HID + hh*32 + cc;
            ks[r][cc] = expf(rowp[CC] - mx) * si;
            vs[r][cc] = rowp[2*CC];
        }
        __syncthreads();
        #pragma unroll
        for (int r = 0; r < 64; r++) acc += ks[r][kk]*vs[r][vv];
        __syncthreads();
    }
    atomicAdd(&kvout[bh*1024 + kk*32 + vv], acc);
}

// ---------------- att = scale * (q@kv) + q * dwconv3x3(v) --------------------
__global__ void att_kernel(const float* __restrict__ qkv, const float* __restrict__ kv,
                           const float* __restrict__ cw, const float* __restrict__ cb,
                           float* __restrict__ att) {
    int bn = blockIdx.x;
    int b = bn >> 14;
    int n = bn & (NN - 1);
    int y = n >> 7, x = n & 127;
    int c = threadIdx.x;
    int hh = c >> 5, dd = c & 31;
    __shared__ float qs[256];
    float qv = qkv[(size_t)bn*HID + c];
    qs[c] = qv;
    __syncthreads();
    float f = 0.f;
    const float* kvp = kv + ((b*8 + hh) << 10) + dd;
    #pragma unroll
    for (int k = 0; k < 32; k++) f += qs[hh*32 + k] * kvp[k*32];
    float cv = cb[c];
    #pragma unroll
    for (int dy = -1; dy <= 1; dy++) {
        int yy = y + dy; if (yy < 0 || yy >= HH_IMG) continue;
        #pragma unroll
        for (int dx = -1; dx <= 1; dx++) {
            int xx = x + dx; if (xx < 0 || xx >= WW_IMG) continue;
            cv += cw[c*9 + (dy+1)*3 + (dx+1)] *
                  qkv[((size_t)b*NN + yy*WW_IMG + xx)*HID + 2*CC + c];
        }
    }
    att[(size_t)bn*CC + c] = 0.17677669529663689f * f + qv * cv;
}

// ---------------- hdn -> gelu(hdn + dwconv3x3(hdn)) --------------------------
__global__ void dcgelu_kernel(const float* __restrict__ hdn, const float* __restrict__ w,
                              const float* __restrict__ bias, float* __restrict__ out) {
    int bn = blockIdx.x;
    int b = bn >> 14;
    int n = bn & (NN - 1);
    int y = n >> 7, x = n & 127;
    for (int c = threadIdx.x; c < HID; c += 256) {
        float center = hdn[(size_t)bn*HID + c];
        float acc = bias[c];
        #pragma unroll
        for (int dy = -1; dy <= 1; dy++) {
            int yy = y + dy; if (yy < 0 || yy >= HH_IMG) continue;
            #pragma unroll
            for (int dx = -1; dx <= 1; dx++) {
                int xx = x + dx; if (xx < 0 || xx >= WW_IMG) continue;
                acc += w[c*9 + (dy+1)*3 + (dx+1)] *
                       hdn[((size_t)b*NN + yy*WW_IMG + xx)*HID + c];
            }
        }
        float tsum = center + acc;
        out[(size_t)bn*HID + c] = 0.5f * tsum * (1.0f + erff(tsum * 0.70710678118654752f));
    }
}

// -----------------------------------------------------------------------------
extern "C" void kernel_launch(void* const* d_in, const int* in_sizes, int n_in,
                              void* d_out, int out_size) {
    const float* x       = (const float*)d_in[0];
    const float* ln1_g   = (const float*)d_in[3];
    const float* ln1_b   = (const float*)d_in[4];
    const float* qkv_w   = (const float*)d_in[5];
    const float* qkv_b   = (const float*)d_in[6];
    const float* crpe_w  = (const float*)d_in[7];
    const float* crpe_b  = (const float*)d_in[8];
    const float* proj_w  = (const float*)d_in[9];
    const float* proj_b  = (const float*)d_in[10];
    const float* ln2_g   = (const float*)d_in[11];
    const float* ln2_b   = (const float*)d_in[12];
    const float* fc1_w   = (const float*)d_in[13];
    const float* fc1_b   = (const float*)d_in[14];
    const float* dconv_w = (const float*)d_in[15];
    const float* dconv_b = (const float*)d_in[16];
    const float* fc2_w   = (const float*)d_in[17];
    const float* fc2_b   = (const float*)d_in[18];
    float* out = (float*)d_out;

    float *p_ln, *p_qkv, *p_att, *p_x2, *p_hdn, *p_act, *p_cmax, *p_csum, *p_kv;
    cudaGetSymbolAddress((void**)&p_ln,   g_ln);
    cudaGetSymbolAddress((void**)&p_qkv,  g_qkv);
    cudaGetSymbolAddress((void**)&p_att,  g_att);
    cudaGetSymbolAddress((void**)&p_x2,   g_x2);
    cudaGetSymbolAddress((void**)&p_hdn,  g_hdn);
    cudaGetSymbolAddress((void**)&p_act,  g_act);
    cudaGetSymbolAddress((void**)&p_cmax, g_cmax);
    cudaGetSymbolAddress((void**)&p_csum, g_csuminv);
    cudaGetSymbolAddress((void**)&p_kv,   g_kv);

    // --- attention branch ---
    ln_kernel<<<MROWS, 256>>>(x, ln1_g, ln1_b, p_ln);
    mma_gemm<false><<<dim3(HID/128, MROWS/128), 256>>>(
        p_ln, qkv_w, qkv_b, nullptr, p_qkv, MROWS, HID, CC);
    colstat_kernel<<<BB*CC, 256>>>(p_qkv, p_cmax, p_csum);
    kv_zero_kernel<<<(BB*NHEAD*DHEAD*DHEAD)/256, 256>>>(p_kv);
    kv_kernel<<<dim3(BB*NHEAD, 16), 1024>>>(p_qkv, p_cmax, p_csum, p_kv);
    att_kernel<<<MROWS, 256>>>(p_qkv, p_kv, crpe_w, crpe_b, p_att);
    mma_gemm<true><<<dim3(CC/128, MROWS/128), 256>>>(
        p_att, proj_w, proj_b, x, p_x2, MROWS, CC, CC);

    // --- conv-MLP branch ---
    ln_kernel<<<MROWS, 256>>>(p_x2, ln2_g, ln2_b, p_ln);
    mma_gemm<false><<<dim3(HID/128, MROWS/128), 256>>>(
        p_ln, fc1_w, fc1_b, nullptr, p_hdn, MROWS, HID, CC);
    dcgelu_kernel<<<MROWS, 256>>>(p_hdn, dconv_w, dconv_b, p_act);
    mma_gemm<true><<<dim3(CC/128, MROWS/128), 256>>>(
        p_act, fc2_w, fc2_b, p_x2, out, MROWS, CC, HID);
}

// round 6
// speedup vs baseline: 2.0075x; 1.2086x over previous
#include <cuda_runtime.h>
#include <cuda_bf16.h>
#include <math.h>
#include <stdint.h>

typedef __nv_bfloat16 bf16;

// Problem constants (B=4, H=W=128, C=256, heads=8, d=32, hid=768)
#define BB 4
#define HH_IMG 128
#define WW_IMG 128
#define NN 16384           // H*W
#define CC 256
#define HID 768
#define NHEAD 8
#define DHEAD 32
#define MROWS (BB*NN)      // 65536

// ---------------- scratch (device globals; no allocation allowed) ------------
__device__ bf16  g_ln [(size_t)MROWS*CC];     // LN output (bf16, GEMM A operand)
__device__ float g_qkv[(size_t)MROWS*HID];    // qkv projection (fp32)
__device__ bf16  g_att[(size_t)MROWS*CC];     // attention output (bf16)
__device__ float g_x2 [(size_t)MROWS*CC];     // x after attention residual
__device__ float g_hdn[(size_t)MROWS*HID];    // fc1 output (fp32)
__device__ bf16  g_act[(size_t)MROWS*HID];    // gelu(hdn + dwconv) (bf16)
__device__ float g_cmax[BB*CC];
__device__ float g_csuminv[BB*CC];
__device__ float g_kv[BB*NHEAD*DHEAD*DHEAD];
// bf16 weights
__device__ bf16 g_wqkv[(size_t)CC*HID];
__device__ bf16 g_wproj[(size_t)CC*CC];
__device__ bf16 g_wfc1[(size_t)CC*HID];
__device__ bf16 g_wfc2[(size_t)HID*CC];

// ---------------- helpers ----------------------------------------------------
__device__ __forceinline__ uint32_t smem_u32(const void* p) {
    return (uint32_t)__cvta_generic_to_shared(p);
}
#define CP_ASYNC16(dst, src) \
    asm volatile("cp.async.cg.shared.global [%0], [%1], 16;" :: "r"(dst), "l"(src))
#define CP_COMMIT() asm volatile("cp.async.commit_group;")
#define CP_WAIT(n)  asm volatile("cp.async.wait_group %0;" :: "n"(n))

__device__ __forceinline__ void ldsm_x4(uint32_t& r0, uint32_t& r1, uint32_t& r2,
                                        uint32_t& r3, uint32_t addr) {
    asm volatile("ldmatrix.sync.aligned.m8n8.x4.shared.b16 {%0,%1,%2,%3}, [%4];"
                 : "=r"(r0), "=r"(r1), "=r"(r2), "=r"(r3) : "r"(addr));
}
__device__ __forceinline__ void ldsm_x4_t(uint32_t& r0, uint32_t& r1, uint32_t& r2,
                                          uint32_t& r3, uint32_t addr) {
    asm volatile("ldmatrix.sync.aligned.m8n8.x4.trans.shared.b16 {%0,%1,%2,%3}, [%4];"
                 : "=r"(r0), "=r"(r1), "=r"(r2), "=r"(r3) : "r"(addr));
}
__device__ __forceinline__ void mma_bf16(float c[4], const uint32_t a[4],
                                         const uint32_t b[2]) {
    asm volatile(
        "mma.sync.aligned.m16n8k16.row.col.f32.bf16.bf16.f32 "
        "{%0,%1,%2,%3}, {%4,%5,%6,%7}, {%8,%9}, {%0,%1,%2,%3};"
        : "+f"(c[0]), "+f"(c[1]), "+f"(c[2]), "+f"(c[3])
        : "r"(a[0]), "r"(a[1]), "r"(a[2]), "r"(a[3]), "r"(b[0]), "r"(b[1]));
}

// ---------------- bf16 tensor-core GEMM: C = A[M,K] @ W[K,N] + bias (+res) ---
// 128x128 CTA tile, BK=32, 256 thr (8 warps, 64x32 each), cp.async double buf.
#define ASTRIDE 40    // halves per A smem row (80B: 8 rows hit 8 distinct 16B slots)
#define BSTRIDE 136   // halves per B smem row (272B: mod 128 = 16, conflict-free)
template <bool RES>
__global__ __launch_bounds__(256, 2)
void mma_gemm(const bf16* __restrict__ A, const bf16* __restrict__ W,
              const float* __restrict__ bias, const float* __restrict__ res,
              float* __restrict__ Cm, int M, int N, int K) {
    __shared__ bf16 As[2][128*ASTRIDE];
    __shared__ bf16 Bs[2][32*BSTRIDE];

    const int tid = threadIdx.x;
    const int wid = tid >> 5;
    const int lane = tid & 31;
    const int grp = lane >> 2;      // 0..7
    const int tig = lane & 3;       // 0..3
    const int rowbase = (wid >> 2) * 64;
    const int colbase = (wid & 3) * 32;
    const int m0 = blockIdx.y * 128;
    const int n0 = blockIdx.x * 128;

    float c[4][4][4];
    #pragma unroll
    for (int mt = 0; mt < 4; mt++)
        #pragma unroll
        for (int nt = 0; nt < 4; nt++)
            #pragma unroll
            for (int j = 0; j < 4; j++) c[mt][nt][j] = 0.f;

    auto load_tiles = [&](int kt, int buf) {
        // A: 128 rows x 32 halves (64B) = 512 x 16B chunks, 2/thread
        #pragma unroll
        for (int i = 0; i < 2; i++) {
            int v = tid + i * 256;
            int r = v >> 2, cq = v & 3;
            const bf16* src = A + (size_t)(m0 + r) * K + kt * 32 + cq * 8;
            CP_ASYNC16(smem_u32(&As[buf][r * ASTRIDE + cq * 8]), src);
        }
        // B: 32 k-rows x 128 halves (256B) = 512 x 16B chunks, 2/thread
        #pragma unroll
        for (int i = 0; i < 2; i++) {
            int v = tid + i * 256;
            int kr = v >> 4, cq = v & 15;
            const bf16* src = W + (size_t)(kt * 32 + kr) * N + n0 + cq * 8;
            CP_ASYNC16(smem_u32(&Bs[buf][kr * BSTRIDE + cq * 8]), src);
        }
        CP_COMMIT();
    };

    const int nkt = K >> 5;
    load_tiles(0, 0);
    for (int kt = 0; kt < nkt; kt++) {
        int buf = kt & 1;
        if (kt + 1 < nkt) { load_tiles(kt + 1, buf ^ 1); CP_WAIT(1); }
        else             { CP_WAIT(0); }
        __syncthreads();

        #pragma unroll
        for (int ks = 0; ks < 2; ks++) {
            // A frags: 4 x ldmatrix.x4 (16 rows x 16 halves each)
            uint32_t af[4][4];
            {
                int r = (lane & 15);
                int kc = ks * 16 + (lane >> 4) * 8;
                #pragma unroll
                for (int mt = 0; mt < 4; mt++) {
                    uint32_t a = smem_u32(
                        &As[buf][(rowbase + mt * 16 + r) * ASTRIDE + kc]);
                    ldsm_x4(af[mt][0], af[mt][1], af[mt][2], af[mt][3], a);
                }
            }
            // B frags: 2 x ldmatrix.x4.trans (16 k x 16 n each -> 2 nt)
            uint32_t bfr[4][2];
            {
                int kr = ks * 16 + (lane & 15);
                #pragma unroll
                for (int np = 0; np < 2; np++) {
                    int nc = colbase + np * 16 + (lane >> 4) * 8;
                    uint32_t a = smem_u32(&Bs[buf][kr * BSTRIDE + nc]);
                    ldsm_x4_t(bfr[np*2][0], bfr[np*2][1],
                              bfr[np*2+1][0], bfr[np*2+1][1], a);
                }
            }
            #pragma unroll
            for (int mt = 0; mt < 4; mt++)
                #pragma unroll
                for (int nt = 0; nt < 4; nt++)
                    mma_bf16(c[mt][nt], af[mt], bfr[nt]);
        }
        __syncthreads();
    }

    // epilogue: c0,c1 -> row grp cols 2tig,2tig+1 ; c2,c3 -> row grp+8
    #pragma unroll
    for (int mt = 0; mt < 4; mt++) {
        #pragma unroll
        for (int nt = 0; nt < 4; nt++) {
            int r = m0 + rowbase + mt * 16 + grp;
            int cn = n0 + colbase + nt * 8 + tig * 2;
            #pragma unroll
            for (int half = 0; half < 2; half++) {
                size_t off = (size_t)(r + half * 8) * N + cn;
                float2 o;
                o.x = c[mt][nt][half*2 + 0] + bias[cn + 0];
                o.y = c[mt][nt][half*2 + 1] + bias[cn + 1];
                if (RES) { o.x += res[off]; o.y += res[off + 1]; }
                *(float2*)(Cm + off) = o;
            }
        }
    }
}

// ---------------- float -> bf16 conversion -----------------------------------
__global__ void f2bf_kernel(const float* __restrict__ in, bf16* __restrict__ out,
                            int n) {
    int i = blockIdx.x * 256 + threadIdx.x;
    if (i < n) out[i] = __float2bfloat16(in[i]);
}

// ---------------- LayerNorm: one block (256 thr) per row, bf16 out -----------
__global__ void ln_kernel(const float* __restrict__ in, const float* __restrict__ g,
                          const float* __restrict__ b, bf16* __restrict__ out) {
    int row = blockIdx.x;
    int t = threadIdx.x;
    float v = in[(size_t)row*CC + t];
    __shared__ float red[256];
    red[t] = v; __syncthreads();
    #pragma unroll
    for (int s = 128; s > 0; s >>= 1) { if (t < s) red[t] += red[t+s]; __syncthreads(); }
    float mean = red[0] * (1.0f/CC);
    __syncthreads();
    float dv = v - mean;
    red[t] = dv*dv; __syncthreads();
    #pragma unroll
    for (int s = 128; s > 0; s >>= 1) { if (t < s) red[t] += red[t+s]; __syncthreads(); }
    float var = red[0] * (1.0f/CC);
    out[(size_t)row*CC + t] =
        __float2bfloat16(dv * rsqrtf(var + 1e-6f) * g[t] + b[t]);
}

// ---------------- Column softmax stats (coalesced online) --------------------
// grid 32 = (b, cgroup of 32 ch); block 256 = 32 ch x 8 token-lanes.
__global__ void colstat_kernel(const float* __restrict__ qkv,
                               float* __restrict__ cmax, float* __restrict__ csuminv) {
    int blk = blockIdx.x;
    int b = blk >> 3, cg = blk & 7;
    int t = threadIdx.x;
    int ci = t & 31, nj = t >> 5;
    const float* base = qkv + (size_t)b*NN*HID + CC + cg*32 + ci;
    float m = -1e30f, s = 0.f;
    for (int n = nj; n < NN; n += 8) {
        float v = base[(size_t)n*HID];
        float mn = fmaxf(m, v);
        s = s * expf(m - mn) + expf(v - mn);
        m = mn;
    }
    __shared__ float sm[8][32], ss[8][32];
    sm[nj][ci] = m; ss[nj][ci] = s;
    __syncthreads();
    if (t < 32) {
        float M = sm[0][t], S = ss[0][t];
        #pragma unroll
        for (int j = 1; j < 8; j++) {
            float mj = sm[j][t], sj = ss[j][t];
            float mn = fmaxf(M, mj);
            S = S * expf(M - mn) + sj * expf(mj - mn);
            M = mn;
        }
        int col = b*256 + cg*32 + t;
        cmax[col] = M; csuminv[col] = 1.0f / S;
    }
}

__global__ void kv_zero_kernel(float* __restrict__ kv) {
    kv[blockIdx.x*256 + threadIdx.x] = 0.f;
}

// ---------------- kv[b,h,k,v] = sum_n softmax(k)[n,k] * v[n,v] ---------------
__global__ __launch_bounds__(1024)
void kv_kernel(const float* __restrict__ qkv, const float* __restrict__ cmax,
               const float* __restrict__ csuminv, float* __restrict__ kvout) {
    int bh = blockIdx.x;
    int b = bh >> 3, hh = bh & 7;
    int t = threadIdx.x;
    int kk = t >> 5, vv = t & 31;
    int cc = t & 31;
    int r0 = t >> 5;
    __shared__ float ks[64][32];
    __shared__ float vs[64][32];
    int colbase = b*256 + hh*32;
    float mx = cmax[colbase + cc];
    float si = csuminv[colbase + cc];
    size_t nbase = (size_t)b*NN + (size_t)blockIdx.y * 1024;
    float acc = 0.f;
    for (int nt = 0; nt < 1024; nt += 64) {
        #pragma unroll
        for (int j = 0; j < 2; j++) {
            int r = r0 + j*32;
            const float* rowp = qkv + (nbase + nt + r)*HID + hh*32 + cc;
            ks[r][cc] = expf(rowp[CC] - mx) * si;
            vs[r][cc] = rowp[2*CC];
        }
        __syncthreads();
        #pragma unroll
        for (int r = 0; r < 64; r++) acc += ks[r][kk]*vs[r][vv];
        __syncthreads();
    }
    atomicAdd(&kvout[bh*1024 + kk*32 + vv], acc);
}

// ---------------- att = scale * (q@kv) + q * dwconv3x3(v), bf16 out ----------
__global__ void att_kernel(const float* __restrict__ qkv, const float* __restrict__ kv,
                           const float* __restrict__ cw, const float* __restrict__ cb,
                           bf16* __restrict__ att) {
    int bn = blockIdx.x;
    int b = bn >> 14;
    int n = bn & (NN - 1);
    int y = n >> 7, x = n & 127;
    int c = threadIdx.x;
    int hh = c >> 5, dd = c & 31;
    __shared__ float qs[256];
    float qv = qkv[(size_t)bn*HID + c];
    qs[c] = qv;
    __syncthreads();
    float f = 0.f;
    const float* kvp = kv + ((b*8 + hh) << 10) + dd;
    #pragma unroll
    for (int k = 0; k < 32; k++) f += qs[hh*32 + k] * kvp[k*32];
    float cv = cb[c];
    #pragma unroll
    for (int dy = -1; dy <= 1; dy++) {
        int yy = y + dy; if (yy < 0 || yy >= HH_IMG) continue;
        #pragma unroll
        for (int dx = -1; dx <= 1; dx++) {
            int xx = x + dx; if (xx < 0 || xx >= WW_IMG) continue;
            cv += cw[c*9 + (dy+1)*3 + (dx+1)] *
                  qkv[((size_t)b*NN + yy*WW_IMG + xx)*HID + 2*CC + c];
        }
    }
    att[(size_t)bn*CC + c] =
        __float2bfloat16(0.17677669529663689f * f + qv * cv);
}

// ---------------- hdn -> gelu(hdn + dwconv3x3(hdn)), bf16 out ----------------
__global__ void dcgelu_kernel(const float* __restrict__ hdn, const float* __restrict__ w,
                              const float* __restrict__ bias, bf16* __restrict__ out) {
    int bn = blockIdx.x;
    int b = bn >> 14;
    int n = bn & (NN - 1);
    int y = n >> 7, x = n & 127;
    for (int c = threadIdx.x; c < HID; c += 256) {
        float center = hdn[(size_t)bn*HID + c];
        float acc = bias[c];
        #pragma unroll
        for (int dy = -1; dy <= 1; dy++) {
            int yy = y + dy; if (yy < 0 || yy >= HH_IMG) continue;
            #pragma unroll
            for (int dx = -1; dx <= 1; dx++) {
                int xx = x + dx; if (xx < 0 || xx >= WW_IMG) continue;
                acc += w[c*9 + (dy+1)*3 + (dx+1)] *
                       hdn[((size_t)b*NN + yy*WW_IMG + xx)*HID + c];
            }
        }
        float tsum = center + acc;
        out[(size_t)bn*HID + c] =
            __float2bfloat16(0.5f * tsum * (1.0f + erff(tsum * 0.70710678118654752f)));
    }
}

// -----------------------------------------------------------------------------
extern "C" void kernel_launch(void* const* d_in, const int* in_sizes, int n_in,
                              void* d_out, int out_size) {
    const float* x       = (const float*)d_in[0];
    const float* ln1_g   = (const float*)d_in[3];
    const float* ln1_b   = (const float*)d_in[4];
    const float* qkv_w   = (const float*)d_in[5];
    const float* qkv_b   = (const float*)d_in[6];
    const float* crpe_w  = (const float*)d_in[7];
    const float* crpe_b  = (const float*)d_in[8];
    const float* proj_w  = (const float*)d_in[9];
    const float* proj_b  = (const float*)d_in[10];
    const float* ln2_g   = (const float*)d_in[11];
    const float* ln2_b   = (const float*)d_in[12];
    const float* fc1_w   = (const float*)d_in[13];
    const float* fc1_b   = (const float*)d_in[14];
    const float* dconv_w = (const float*)d_in[15];
    const float* dconv_b = (const float*)d_in[16];
    const float* fc2_w   = (const float*)d_in[17];
    const float* fc2_b   = (const float*)d_in[18];
    float* out = (float*)d_out;

    bf16 *p_ln, *p_att, *p_act, *p_wqkv, *p_wproj, *p_wfc1, *p_wfc2;
    float *p_qkv, *p_x2, *p_hdn, *p_cmax, *p_csum, *p_kv;
    cudaGetSymbolAddress((void**)&p_ln,   g_ln);
    cudaGetSymbolAddress((void**)&p_qkv,  g_qkv);
    cudaGetSymbolAddress((void**)&p_att,  g_att);
    cudaGetSymbolAddress((void**)&p_x2,   g_x2);
    cudaGetSymbolAddress((void**)&p_hdn,  g_hdn);
    cudaGetSymbolAddress((void**)&p_act,  g_act);
    cudaGetSymbolAddress((void**)&p_cmax, g_cmax);
    cudaGetSymbolAddress((void**)&p_csum, g_csuminv);
    cudaGetSymbolAddress((void**)&p_kv,   g_kv);
    cudaGetSymbolAddress((void**)&p_wqkv, g_wqkv);
    cudaGetSymbolAddress((void**)&p_wproj,g_wproj);
    cudaGetSymbolAddress((void**)&p_wfc1, g_wfc1);
    cudaGetSymbolAddress((void**)&p_wfc2, g_wfc2);

    // weights -> bf16
    f2bf_kernel<<<(CC*HID+255)/256, 256>>>(qkv_w, p_wqkv, CC*HID);
    f2bf_kernel<<<(CC*CC +255)/256, 256>>>(proj_w, p_wproj, CC*CC);
    f2bf_kernel<<<(CC*HID+255)/256, 256>>>(fc1_w, p_wfc1, CC*HID);
    f2bf_kernel<<<(HID*CC+255)/256, 256>>>(fc2_w, p_wfc2, HID*CC);

    // --- attention branch ---
    ln_kernel<<<MROWS, 256>>>(x, ln1_g, ln1_b, p_ln);
    mma_gemm<false><<<dim3(HID/128, MROWS/128), 256>>>(
        p_ln, p_wqkv, qkv_b, nullptr, p_qkv, MROWS, HID, CC);
    colstat_kernel<<<BB*NHEAD, 256>>>(p_qkv, p_cmax, p_csum);
    kv_zero_kernel<<<(BB*NHEAD*DHEAD*DHEAD)/256, 256>>>(p_kv);
    kv_kernel<<<dim3(BB*NHEAD, 16), 1024>>>(p_qkv, p_cmax, p_csum, p_kv);
    att_kernel<<<MROWS, 256>>>(p_qkv, p_kv, crpe_w, crpe_b, p_att);
    mma_gemm<true><<<dim3(CC/128, MROWS/128), 256>>>(
        p_att, p_wproj, proj_b, x, p_x2, MROWS, CC, CC);

    // --- conv-MLP branch ---
    ln_kernel<<<MROWS, 256>>>(p_x2, ln2_g, ln2_b, p_ln);
    mma_gemm<false><<<dim3(HID/128, MROWS/128), 256>>>(
        p_ln, p_wfc1, fc1_b, nullptr, p_hdn, MROWS, HID, CC);
    dcgelu_kernel<<<MROWS, 256>>>(p_hdn, dconv_w, dconv_b, p_act);
    mma_gemm<true><<<dim3(CC/128, MROWS/128), 256>>>(
        p_act, p_wfc2, fc2_b, p_x2, out, MROWS, CC, HID);
}

// round 11
// speedup vs baseline: 2.1211x; 1.0566x over previous
#include <cuda_runtime.h>
#include <cuda_bf16.h>
#include <math.h>
#include <stdint.h>

typedef __nv_bfloat16 bf16;

// Problem constants (B=4, H=W=128, C=256, heads=8, d=32, hid=768)
#define BB 4
#define HH_IMG 128
#define WW_IMG 128
#define NN 16384           // H*W
#define CC 256
#define HID 768
#define NHEAD 8
#define DHEAD 32
#define MROWS (BB*NN)      // 65536

// ---------------- scratch (device globals; no allocation allowed) ------------
__device__ bf16  g_ln [(size_t)MROWS*CC];     // LN output (bf16, GEMM A operand)
__device__ float g_qkv[(size_t)MROWS*HID];    // qkv projection (fp32)
__device__ bf16  g_att[(size_t)MROWS*CC];     // attention output (bf16)
__device__ float g_x2 [(size_t)MROWS*CC];     // x after attention residual
__device__ float g_hdn[(size_t)MROWS*HID];    // fc1 output (fp32)
__device__ bf16  g_act[(size_t)MROWS*HID];    // gelu(hdn + dwconv) (bf16)
__device__ float g_cmax[BB*CC];
__device__ float g_csuminv[BB*CC];
__device__ float g_kv[BB*NHEAD*DHEAD*DHEAD];
// bf16 weights
__device__ bf16 g_wqkv[(size_t)CC*HID];
__device__ bf16 g_wproj[(size_t)CC*CC];
__device__ bf16 g_wfc1[(size_t)CC*HID];
__device__ bf16 g_wfc2[(size_t)HID*CC];

// ---------------- helpers ----------------------------------------------------
__device__ __forceinline__ uint32_t smem_u32(const void* p) {
    return (uint32_t)__cvta_generic_to_shared(p);
}
#define CP_ASYNC16(dst, src) \
    asm volatile("cp.async.cg.shared.global [%0], [%1], 16;" :: "r"(dst), "l"(src))
#define CP_COMMIT() asm volatile("cp.async.commit_group;")
#define CP_WAIT(n)  asm volatile("cp.async.wait_group %0;" :: "n"(n))

__device__ __forceinline__ void ldsm_x4(uint32_t& r0, uint32_t& r1, uint32_t& r2,
                                        uint32_t& r3, uint32_t addr) {
    asm volatile("ldmatrix.sync.aligned.m8n8.x4.shared.b16 {%0,%1,%2,%3}, [%4];"
                 : "=r"(r0), "=r"(r1), "=r"(r2), "=r"(r3) : "r"(addr));
}
__device__ __forceinline__ void ldsm_x4_t(uint32_t& r0, uint32_t& r1, uint32_t& r2,
                                          uint32_t& r3, uint32_t addr) {
    asm volatile("ldmatrix.sync.aligned.m8n8.x4.trans.shared.b16 {%0,%1,%2,%3}, [%4];"
                 : "=r"(r0), "=r"(r1), "=r"(r2), "=r"(r3) : "r"(addr));
}
__device__ __forceinline__ void mma_bf16(float c[4], const uint32_t a[4],
                                         const uint32_t b[2]) {
    asm volatile(
        "mma.sync.aligned.m16n8k16.row.col.f32.bf16.bf16.f32 "
        "{%0,%1,%2,%3}, {%4,%5,%6,%7}, {%8,%9}, {%0,%1,%2,%3};"
        : "+f"(c[0]), "+f"(c[1]), "+f"(c[2]), "+f"(c[3])
        : "r"(a[0]), "r"(a[1]), "r"(a[2]), "r"(a[3]), "r"(b[0]), "r"(b[1]));
}

// ---------------- bf16 tensor-core GEMM: C = A[M,K] @ W[K,N] + bias (+res) ---
// 128x128 CTA tile, BK=32, 256 thr (8 warps, 64x32 each), cp.async double buf,
// fragment prefetch across the two k16 stages.
#define ASTRIDE 40    // halves per A smem row (80B: 8 rows hit 8 distinct 16B slots)
#define BSTRIDE 136   // halves per B smem row (272B: mod 128 = 16, conflict-free)
template <bool RES>
__global__ __launch_bounds__(256, 2)
void mma_gemm(const bf16* __restrict__ A, const bf16* __restrict__ W,
              const float* __restrict__ bias, const float* __restrict__ res,
              float* __restrict__ Cm, int M, int N, int K) {
    __shared__ bf16 As[2][128*ASTRIDE];
    __shared__ bf16 Bs[2][32*BSTRIDE];

    const int tid = threadIdx.x;
    const int wid = tid >> 5;
    const int lane = tid & 31;
    const int grp = lane >> 2;      // 0..7
    const int tig = lane & 3;       // 0..3
    const int rowbase = (wid >> 2) * 64;
    const int colbase = (wid & 3) * 32;
    const int m0 = blockIdx.y * 128;
    const int n0 = blockIdx.x * 128;

    float c[4][4][4];
    #pragma unroll
    for (int mt = 0; mt < 4; mt++)
        #pragma unroll
        for (int nt = 0; nt < 4; nt++)
            #pragma unroll
            for (int j = 0; j < 4; j++) c[mt][nt][j] = 0.f;

    auto load_tiles = [&](int kt, int buf) {
        #pragma unroll
        for (int i = 0; i < 2; i++) {
            int v = tid + i * 256;
            int r = v >> 2, cq = v & 3;
            const bf16* src = A + (size_t)(m0 + r) * K + kt * 32 + cq * 8;
            CP_ASYNC16(smem_u32(&As[buf][r * ASTRIDE + cq * 8]), src);
        }
        #pragma unroll
        for (int i = 0; i < 2; i++) {
            int v = tid + i * 256;
            int kr = v >> 4, cq = v & 15;
            const bf16* src = W + (size_t)(kt * 32 + kr) * N + n0 + cq * 8;
            CP_ASYNC16(smem_u32(&Bs[buf][kr * BSTRIDE + cq * 8]), src);
        }
        CP_COMMIT();
    };

    auto ldfrags = [&](int buf, int ks, uint32_t af[4][4], uint32_t bfr[4][2]) {
        int r = (lane & 15);
        int kc = ks * 16 + (lane >> 4) * 8;
        #pragma unroll
        for (int mt = 0; mt < 4; mt++) {
            uint32_t a = smem_u32(&As[buf][(rowbase + mt * 16 + r) * ASTRIDE + kc]);
            ldsm_x4(af[mt][0], af[mt][1], af[mt][2], af[mt][3], a);
        }
        int kr = ks * 16 + (lane & 15);
        #pragma unroll
        for (int np = 0; np < 2; np++) {
            int nc = colbase + np * 16 + (lane >> 4) * 8;
            uint32_t a = smem_u32(&Bs[buf][kr * BSTRIDE + nc]);
            ldsm_x4_t(bfr[np*2][0], bfr[np*2][1], bfr[np*2+1][0], bfr[np*2+1][1], a);
        }
    };

    const int nkt = K >> 5;
    load_tiles(0, 0);
    for (int kt = 0; kt < nkt; kt++) {
        int buf = kt & 1;
        if (kt + 1 < nkt) { load_tiles(kt + 1, buf ^ 1); CP_WAIT(1); }
        else             { CP_WAIT(0); }
        __syncthreads();

        uint32_t af[2][4][4], bfr[2][4][2];
        ldfrags(buf, 0, af[0], bfr[0]);
        ldfrags(buf, 1, af[1], bfr[1]);
        #pragma unroll
        for (int ks = 0; ks < 2; ks++)
            #pragma unroll
            for (int mt = 0; mt < 4; mt++)
                #pragma unroll
                for (int nt = 0; nt < 4; nt++)
                    mma_bf16(c[mt][nt], af[ks][mt], bfr[ks][nt]);
        __syncthreads();
    }

    // epilogue: c0,c1 -> row grp cols 2tig,2tig+1 ; c2,c3 -> row grp+8
    #pragma unroll
    for (int mt = 0; mt < 4; mt++) {
        #pragma unroll
        for (int nt = 0; nt < 4; nt++) {
            int r = m0 + rowbase + mt * 16 + grp;
            int cn = n0 + colbase + nt * 8 + tig * 2;
            #pragma unroll
            for (int half = 0; half < 2; half++) {
                size_t off = (size_t)(r + half * 8) * N + cn;
                float2 o;
                o.x = c[mt][nt][half*2 + 0] + bias[cn + 0];
                o.y = c[mt][nt][half*2 + 1] + bias[cn + 1];
                if (RES) { o.x += res[off]; o.y += res[off + 1]; }
                *(float2*)(Cm + off) = o;
            }
        }
    }
}

// ---------------- float -> bf16 conversion -----------------------------------
__global__ void f2bf_kernel(const float* __restrict__ in, bf16* __restrict__ out,
                            int n) {
    int i = blockIdx.x * 256 + threadIdx.x;
    if (i < n) out[i] = __float2bfloat16(in[i]);
}

// ---------------- LayerNorm: warp per row, no block syncs, bf16 out ----------
__global__ __launch_bounds__(256)
void ln_kernel(const float* __restrict__ in, const float* __restrict__ g,
               const float* __restrict__ b, bf16* __restrict__ out) {
    int wid = threadIdx.x >> 5, lane = threadIdx.x & 31;
    size_t row = (size_t)blockIdx.x * 8 + wid;
    const float* p = in + row * CC + lane * 8;
    float4 v0 = *(const float4*)p;
    float4 v1 = *(const float4*)(p + 4);
    float v[8] = {v0.x, v0.y, v0.z, v0.w, v1.x, v1.y, v1.z, v1.w};
    float s1 = 0.f, s2 = 0.f;
    #pragma unroll
    for (int j = 0; j < 8; j++) { s1 += v[j]; s2 += v[j]*v[j]; }
    #pragma unroll
    for (int o = 16; o > 0; o >>= 1) {
        s1 += __shfl_xor_sync(0xffffffffu, s1, o);
        s2 += __shfl_xor_sync(0xffffffffu, s2, o);
    }
    float mean = s1 * (1.0f/CC);
    float var  = s2 * (1.0f/CC) - mean * mean;
    float rstd = rsqrtf(var + 1e-6f);
    const float* gp = g + lane * 8;
    const float* bp = b + lane * 8;
    float4 g0 = *(const float4*)gp, g1 = *(const float4*)(gp + 4);
    float4 b0 = *(const float4*)bp, b1 = *(const float4*)(bp + 4);
    float gg[8] = {g0.x, g0.y, g0.z, g0.w, g1.x, g1.y, g1.z, g1.w};
    float bb2[8] = {b0.x, b0.y, b0.z, b0.w, b1.x, b1.y, b1.z, b1.w};
    bf16 o8[8];
    #pragma unroll
    for (int j = 0; j < 8; j++)
        o8[j] = __float2bfloat16((v[j] - mean) * rstd * gg[j] + bb2[j]);
    *(uint4*)(out + row * CC + lane * 8) = *(uint4*)o8;
}

// ---------------- Column softmax stats (coalesced online) --------------------
__global__ void colstat_kernel(const float* __restrict__ qkv,
                               float* __restrict__ cmax, float* __restrict__ csuminv) {
    int blk = blockIdx.x;
    int b = blk >> 3, cg = blk & 7;
    int t = threadIdx.x;
    int ci = t & 31, nj = t >> 5;
    const float* base = qkv + (size_t)b*NN*HID + CC + cg*32 + ci;
    float m = -1e30f, s = 0.f;
    for (int n = nj; n < NN; n += 8) {
        float v = base[(size_t)n*HID];
        float mn = fmaxf(m, v);
        s = s * expf(m - mn) + expf(v - mn);
        m = mn;
    }
    __shared__ float sm[8][32], ss[8][32];
    sm[nj][ci] = m; ss[nj][ci] = s;
    __syncthreads();
    if (t < 32) {
        float M = sm[0][t], S = ss[0][t];
        #pragma unroll
        for (int j = 1; j < 8; j++) {
            float mj = sm[j][t], sj = ss[j][t];
            float mn = fmaxf(M, mj);
            S = S * expf(M - mn) + sj * expf(mj - mn);
            M = mn;
        }
        int col = b*256 + cg*32 + t;
        cmax[col] = M; csuminv[col] = 1.0f / S;
    }
}

__global__ void kv_zero_kernel(float* __restrict__ kv) {
    kv[blockIdx.x*256 + threadIdx.x] = 0.f;
}

// ---------------- kv[b,h,k,v] = sum_n softmax(k)[n,k] * v[n,v] ---------------
__global__ __launch_bounds__(1024)
void kv_kernel(const float* __restrict__ qkv, const float* __restrict__ cmax,
               const float* __restrict__ csuminv, float* __restrict__ kvout) {
    int bh = blockIdx.x;
    int b = bh >> 3, hh = bh & 7;
    int t = threadIdx.x;
    int kk = t >> 5, vv = t & 31;
    int cc = t & 31;
    int r0 = t >> 5;
    __shared__ float ks[64][32];
    __shared__ float vs[64][32];
    int colbase = b*256 + hh*32;
    float mx = cmax[colbase + cc];
    float si = csuminv[colbase + cc];
    size_t nbase = (size_t)b*NN + (size_t)blockIdx.y * 1024;
    float acc = 0.f;
    for (int nt = 0; nt < 1024; nt += 64) {
        #pragma unroll
        for (int j = 0; j < 2; j++) {
            int r = r0 + j*32;
            const float* rowp = qkv + (nbase + nt + r)*HID + hh*32 + cc;
            ks[r][cc] = expf(rowp[CC] - mx) * si;
            vs[r][cc] = rowp[2*CC];
        }
        __syncthreads();
        #pragma unroll
        for (int r = 0; r < 64; r++) acc += ks[r][kk]*vs[r][vv];
        __syncthreads();
    }
    atomicAdd(&kvout[bh*1024 + kk*32 + vv], acc);
}

// ---------------- att = scale * (q@kv) + q * dwconv3x3(v), bf16 out ----------
__global__ void att_kernel(const float* __restrict__ qkv, const float* __restrict__ kv,
                           const float* __restrict__ cw, const float* __restrict__ cb,
                           bf16* __restrict__ att) {
    int bn = blockIdx.x;
    int b = bn >> 14;
    int n = bn & (NN - 1);
    int y = n >> 7, x = n & 127;
    int c = threadIdx.x;
    int hh = c >> 5, dd = c & 31;
    __shared__ float qs[256];
    float qv = qkv[(size_t)bn*HID + c];
    qs[c] = qv;
    __syncthreads();
    float f = 0.f;
    const float* kvp = kv + ((b*8 + hh) << 10) + dd;
    #pragma unroll
    for (int k = 0; k < 32; k++) f += qs[hh*32 + k] * kvp[k*32];
    float cv = cb[c];
    #pragma unroll
    for (int dy = -1; dy <= 1; dy++) {
        int yy = y + dy; if (yy < 0 || yy >= HH_IMG) continue;
        #pragma unroll
        for (int dx = -1; dx <= 1; dx++) {
            int xx = x + dx; if (xx < 0 || xx >= WW_IMG) continue;
            cv += cw[c*9 + (dy+1)*3 + (dx+1)] *
                  qkv[((size_t)b*NN + yy*WW_IMG + xx)*HID + 2*CC + c];
        }
    }
    att[(size_t)bn*CC + c] =
        __float2bfloat16(0.17677669529663689f * f + qv * cv);
}

// ---------------- dcgelu: smem-tiled 8x8x96, gelu(hdn + dwconv3x3(hdn)) ------
#define DC_CH 96
__global__ __launch_bounds__(256)
void dcgelu_kernel(const float* __restrict__ hdn, const float* __restrict__ w,
                   const float* __restrict__ bias, bf16* __restrict__ out) {
    int blk = blockIdx.x;          // 8192 = 1024 tiles x 8 cgroups
    int cg = blk & 7;
    int tile = blk >> 3;
    int b = tile >> 8;
    int t16 = tile & 255;
    int ty = t16 >> 4, tx = t16 & 15;
    int y0 = ty * 8, x0 = tx * 8;
    __shared__ float sm[100 * DC_CH];      // 10x10 halo tile, ch-contig
    __shared__ float sw[DC_CH * 9];
    __shared__ float sb[DC_CH];
    int tid = threadIdx.x;
    for (int i = tid; i < DC_CH * 9; i += 256) sw[i] = w[cg * DC_CH * 9 + i];
    for (int i = tid; i < DC_CH; i += 256) sb[i] = bias[cg * DC_CH + i];
    for (int i = tid; i < 100 * DC_CH; i += 256) {
        int ch = i % DC_CH, pos = i / DC_CH;
        int yy = pos / 10, xx = pos % 10;
        int gy = y0 + yy - 1, gx = x0 + xx - 1;
        float v = 0.f;
        if (gy >= 0 && gy < HH_IMG && gx >= 0 && gx < WW_IMG)
            v = hdn[((size_t)b*NN + gy*WW_IMG + gx)*HID + cg*DC_CH + ch];
        sm[i] = v;
    }
    __syncthreads();
    for (int o = tid; o < 64 * DC_CH; o += 256) {
        int ch = o % DC_CH, pos = o / DC_CH;
        int oy = pos >> 3, ox = pos & 7;
        float center = sm[((oy+1)*10 + (ox+1))*DC_CH + ch];
        float acc = sb[ch];
        #pragma unroll
        for (int dy = 0; dy < 3; dy++)
            #pragma unroll
            for (int dx = 0; dx < 3; dx++)
                acc += sw[ch*9 + dy*3 + dx] * sm[((oy+dy)*10 + (ox+dx))*DC_CH + ch];
        float ts = center + acc;
        out[((size_t)b*NN + (y0+oy)*WW_IMG + (x0+ox))*HID + cg*DC_CH + ch] =
            __float2bfloat16(0.5f * ts * (1.0f + erff(ts * 0.70710678118654752f)));
    }
}

// -----------------------------------------------------------------------------
extern "C" void kernel_launch(void* const* d_in, const int* in_sizes, int n_in,
                              void* d_out, int out_size) {
    const float* x       = (const float*)d_in[0];
    const float* ln1_g   = (const float*)d_in[3];
    const float* ln1_b   = (const float*)d_in[4];
    const float* qkv_w   = (const float*)d_in[5];
    const float* qkv_b   = (const float*)d_in[6];
    const float* crpe_w  = (const float*)d_in[7];
    const float* crpe_b  = (const float*)d_in[8];
    const float* proj_w  = (const float*)d_in[9];
    const float* proj_b  = (const float*)d_in[10];
    const float* ln2_g   = (const float*)d_in[11];
    const float* ln2_b   = (const float*)d_in[12];
    const float* fc1_w   = (const float*)d_in[13];
    const float* fc1_b   = (const float*)d_in[14];
    const float* dconv_w = (const float*)d_in[15];
    const float* dconv_b = (const float*)d_in[16];
    const float* fc2_w   = (const float*)d_in[17];
    const float* fc2_b   = (const float*)d_in[18];
    float* out = (float*)d_out;

    bf16 *p_ln, *p_att, *p_act, *p_wqkv, *p_wproj, *p_wfc1, *p_wfc2;
    float *p_qkv, *p_x2, *p_hdn, *p_cmax, *p_csum, *p_kv;
    cudaGetSymbolAddress((void**)&p_ln,   g_ln);
    cudaGetSymbolAddress((void**)&p_qkv,  g_qkv);
    cudaGetSymbolAddress((void**)&p_att,  g_att);
    cudaGetSymbolAddress((void**)&p_x2,   g_x2);
    cudaGetSymbolAddress((void**)&p_hdn,  g_hdn);
    cudaGetSymbolAddress((void**)&p_act,  g_act);
    cudaGetSymbolAddress((void**)&p_cmax, g_cmax);
    cudaGetSymbolAddress((void**)&p_csum, g_csuminv);
    cudaGetSymbolAddress((void**)&p_kv,   g_kv);
    cudaGetSymbolAddress((void**)&p_wqkv, g_wqkv);
    cudaGetSymbolAddress((void**)&p_wproj,g_wproj);
    cudaGetSymbolAddress((void**)&p_wfc1, g_wfc1);
    cudaGetSymbolAddress((void**)&p_wfc2, g_wfc2);

    // launch order arranged so the qkv GEMM is launch index 3 (profiler slot)
    f2bf_kernel<<<(CC*HID+255)/256, 256>>>(qkv_w, p_wqkv, CC*HID);      // 0
    f2bf_kernel<<<(CC*CC +255)/256, 256>>>(proj_w, p_wproj, CC*CC);     // 1
    ln_kernel<<<MROWS/8, 256>>>(x, ln1_g, ln1_b, p_ln);                 // 2
    mma_gemm<false><<<dim3(HID/128, MROWS/128), 256>>>(                 // 3 <- prof
        p_ln, p_wqkv, qkv_b, nullptr, p_qkv, MROWS, HID, CC);
    colstat_kernel<<<BB*NHEAD, 256>>>(p_qkv, p_cmax, p_csum);           // 4
    kv_zero_kernel<<<(BB*NHEAD*DHEAD*DHEAD)/256, 256>>>(p_kv);          // 5
    kv_kernel<<<dim3(BB*NHEAD, 16), 1024>>>(p_qkv, p_cmax, p_csum, p_kv); // 6
    att_kernel<<<MROWS, 256>>>(p_qkv, p_kv, crpe_w, crpe_b, p_att);     // 7
    mma_gemm<true><<<dim3(CC/128, MROWS/128), 256>>>(                   // 8
        p_att, p_wproj, proj_b, x, p_x2, MROWS, CC, CC);

    f2bf_kernel<<<(CC*HID+255)/256, 256>>>(fc1_w, p_wfc1, CC*HID);      // 9
    ln_kernel<<<MROWS/8, 256>>>(p_x2, ln2_g, ln2_b, p_ln);              // 10
    mma_gemm<false><<<dim3(HID/128, MROWS/128), 256>>>(                 // 11
        p_ln, p_wfc1, fc1_b, nullptr, p_hdn, MROWS, HID, CC);
    f2bf_kernel<<<(HID*CC+255)/256, 256>>>(fc2_w, p_wfc2, HID*CC);      // 12
    dcgelu_kernel<<<MROWS/8, 256>>>(p_hdn, dconv_w, dconv_b, p_act);    // 13
    mma_gemm<true><<<dim3(CC/128, MROWS/128), 256>>>(                   // 14
        p_act, p_wfc2, fc2_b, p_x2, out, MROWS, CC, HID);
}

// round 15
// speedup vs baseline: 2.1568x; 1.0168x over previous
#include <cuda_runtime.h>
#include <cuda_bf16.h>
#include <math.h>
#include <stdint.h>

typedef __nv_bfloat16 bf16;

// Problem constants (B=4, H=W=128, C=256, heads=8, d=32, hid=768)
#define BB 4
#define HH_IMG 128
#define WW_IMG 128
#define NN 16384           // H*W
#define CC 256
#define HID 768
#define NHEAD 8
#define DHEAD 32
#define MROWS (BB*NN)      // 65536

// ---------------- scratch (device globals; no allocation allowed) ------------
__device__ bf16  g_ln [(size_t)MROWS*CC];     // LN output (bf16, GEMM A operand)
__device__ bf16  g_qkv[(size_t)MROWS*HID];    // qkv projection (bf16)
__device__ bf16  g_att[(size_t)MROWS*CC];     // attention output (bf16)
__device__ float g_x2 [(size_t)MROWS*CC];     // x after attention residual (fp32)
__device__ bf16  g_hdn[(size_t)MROWS*HID];    // fc1 output (bf16)
__device__ bf16  g_act[(size_t)MROWS*HID];    // gelu(hdn + dwconv) (bf16)
__device__ float g_cmax[BB*CC];
__device__ float g_csuminv[BB*CC];
__device__ float g_kv[BB*NHEAD*DHEAD*DHEAD];
// bf16 weights
__device__ bf16 g_wqkv[(size_t)CC*HID];
__device__ bf16 g_wproj[(size_t)CC*CC];
__device__ bf16 g_wfc1[(size_t)CC*HID];
__device__ bf16 g_wfc2[(size_t)HID*CC];

// ---------------- helpers ----------------------------------------------------
__device__ __forceinline__ uint32_t smem_u32(const void* p) {
    return (uint32_t)__cvta_generic_to_shared(p);
}
#define CP_ASYNC16(dst, src) \
    asm volatile("cp.async.cg.shared.global [%0], [%1], 16;" :: "r"(dst), "l"(src))
#define CP_COMMIT() asm volatile("cp.async.commit_group;")
#define CP_WAIT(n)  asm volatile("cp.async.wait_group %0;" :: "n"(n))

__device__ __forceinline__ void ldsm_x4(uint32_t& r0, uint32_t& r1, uint32_t& r2,
                                        uint32_t& r3, uint32_t addr) {
    asm volatile("ldmatrix.sync.aligned.m8n8.x4.shared.b16 {%0,%1,%2,%3}, [%4];"
                 : "=r"(r0), "=r"(r1), "=r"(r2), "=r"(r3) : "r"(addr));
}
__device__ __forceinline__ void ldsm_x4_t(uint32_t& r0, uint32_t& r1, uint32_t& r2,
                                          uint32_t& r3, uint32_t addr) {
    asm volatile("ldmatrix.sync.aligned.m8n8.x4.trans.shared.b16 {%0,%1,%2,%3}, [%4];"
                 : "=r"(r0), "=r"(r1), "=r"(r2), "=r"(r3) : "r"(addr));
}
__device__ __forceinline__ void mma_bf16(float c[4], const uint32_t a[4],
                                         const uint32_t b[2]) {
    asm volatile(
        "mma.sync.aligned.m16n8k16.row.col.f32.bf16.bf16.f32 "
        "{%0,%1,%2,%3}, {%4,%5,%6,%7}, {%8,%9}, {%0,%1,%2,%3};"
        : "+f"(c[0]), "+f"(c[1]), "+f"(c[2]), "+f"(c[3])
        : "r"(a[0]), "r"(a[1]), "r"(a[2]), "r"(a[3]), "r"(b[0]), "r"(b[1]));
}

// output stores: fp32 pair or packed bf16x2
__device__ __forceinline__ void store2(float* p, float x, float y) {
    *(float2*)p = make_float2(x, y);
}
__device__ __forceinline__ void store2(bf16* p, float x, float y) {
    __nv_bfloat162 h = __floats2bfloat162_rn(x, y);
    *(__nv_bfloat162*)p = h;
}

// ---------------- bf16 tensor-core GEMM: C = A[M,K] @ W[K,N] + bias (+res) ---
// 128x128 CTA tile, BK=32, 256 thr (8 warps, 64x32 each), cp.async double buf,
// fragment prefetch across the two k16 stages. OutT = float or bf16.
#define ASTRIDE 40    // halves per A smem row (80B: 8 rows hit 8 distinct 16B slots)
#define BSTRIDE 136   // halves per B smem row (272B: mod 128 = 16, conflict-free)
template <bool RES, typename OutT>
__global__ __launch_bounds__(256, 2)
void mma_gemm(const bf16* __restrict__ A, const bf16* __restrict__ W,
              const float* __restrict__ bias, const float* __restrict__ res,
              OutT* __restrict__ Cm, int M, int N, int K) {
    __shared__ bf16 As[2][128*ASTRIDE];
    __shared__ bf16 Bs[2][32*BSTRIDE];

    const int tid = threadIdx.x;
    const int wid = tid >> 5;
    const int lane = tid & 31;
    const int grp = lane >> 2;      // 0..7
    const int tig = lane & 3;       // 0..3
    const int rowbase = (wid >> 2) * 64;
    const int colbase = (wid & 3) * 32;
    const int m0 = blockIdx.y * 128;
    const int n0 = blockIdx.x * 128;

    float c[4][4][4];
    #pragma unroll
    for (int mt = 0; mt < 4; mt++)
        #pragma unroll
        for (int nt = 0; nt < 4; nt++)
            #pragma unroll
            for (int j = 0; j < 4; j++) c[mt][nt][j] = 0.f;

    auto load_tiles = [&](int kt, int buf) {
        #pragma unroll
        for (int i = 0; i < 2; i++) {
            int v = tid + i * 256;
            int r = v >> 2, cq = v & 3;
            const bf16* src = A + (size_t)(m0 + r) * K + kt * 32 + cq * 8;
            CP_ASYNC16(smem_u32(&As[buf][r * ASTRIDE + cq * 8]), src);
        }
        #pragma unroll
        for (int i = 0; i < 2; i++) {
            int v = tid + i * 256;
            int kr = v >> 4, cq = v & 15;
            const bf16* src = W + (size_t)(kt * 32 + kr) * N + n0 + cq * 8;
            CP_ASYNC16(smem_u32(&Bs[buf][kr * BSTRIDE + cq * 8]), src);
        }
        CP_COMMIT();
    };

    auto ldfrags = [&](int buf, int ks, uint32_t af[4][4], uint32_t bfr[4][2]) {
        int r = (lane & 15);
        int kc = ks * 16 + (lane >> 4) * 8;
        #pragma unroll
        for (int mt = 0; mt < 4; mt++) {
            uint32_t a = smem_u32(&As[buf][(rowbase + mt * 16 + r) * ASTRIDE + kc]);
            ldsm_x4(af[mt][0], af[mt][1], af[mt][2], af[mt][3], a);
        }
        int kr = ks * 16 + (lane & 15);
        #pragma unroll
        for (int np = 0; np < 2; np++) {
            int nc = colbase + np * 16 + (lane >> 4) * 8;
            uint32_t a = smem_u32(&Bs[buf][kr * BSTRIDE + nc]);
            ldsm_x4_t(bfr[np*2][0], bfr[np*2][1], bfr[np*2+1][0], bfr[np*2+1][1], a);
        }
    };

    const int nkt = K >> 5;
    load_tiles(0, 0);
    for (int kt = 0; kt < nkt; kt++) {
        int buf = kt & 1;
        if (kt + 1 < nkt) { load_tiles(kt + 1, buf ^ 1); CP_WAIT(1); }
        else             { CP_WAIT(0); }
        __syncthreads();

        uint32_t af[2][4][4], bfr[2][4][2];
        ldfrags(buf, 0, af[0], bfr[0]);
        ldfrags(buf, 1, af[1], bfr[1]);
        #pragma unroll
        for (int ks = 0; ks < 2; ks++)
            #pragma unroll
            for (int mt = 0; mt < 4; mt++)
                #pragma unroll
                for (int nt = 0; nt < 4; nt++)
                    mma_bf16(c[mt][nt], af[ks][mt], bfr[ks][nt]);
        __syncthreads();
    }

    // epilogue: c0,c1 -> row grp cols 2tig,2tig+1 ; c2,c3 -> row grp+8
    #pragma unroll
    for (int mt = 0; mt < 4; mt++) {
        #pragma unroll
        for (int nt = 0; nt < 4; nt++) {
            int r = m0 + rowbase + mt * 16 + grp;
            int cn = n0 + colbase + nt * 8 + tig * 2;
            #pragma unroll
            for (int half = 0; half < 2; half++) {
                size_t off = (size_t)(r + half * 8) * N + cn;
                float ox = c[mt][nt][half*2 + 0] + bias[cn + 0];
                float oy = c[mt][nt][half*2 + 1] + bias[cn + 1];
                if (RES) { ox += res[off]; oy += res[off + 1]; }
                store2(Cm + off, ox, oy);
            }
        }
    }
}

// ---------------- float -> bf16 conversion -----------------------------------
__global__ void f2bf_kernel(const float* __restrict__ in, bf16* __restrict__ out,
                            int n) {
    int i = blockIdx.x * 256 + threadIdx.x;
    if (i < n) out[i] = __float2bfloat16(in[i]);
}

// ---------------- LayerNorm: warp per row, no block syncs, bf16 out ----------
__global__ __launch_bounds__(256)
void ln_kernel(const float* __restrict__ in, const float* __restrict__ g,
               const float* __restrict__ b, bf16* __restrict__ out) {
    int wid = threadIdx.x >> 5, lane = threadIdx.x & 31;
    size_t row = (size_t)blockIdx.x * 8 + wid;
    const float* p = in + row * CC + lane * 8;
    float4 v0 = *(const float4*)p;
    float4 v1 = *(const float4*)(p + 4);
    float v[8] = {v0.x, v0.y, v0.z, v0.w, v1.x, v1.y, v1.z, v1.w};
    float s1 = 0.f, s2 = 0.f;
    #pragma unroll
    for (int j = 0; j < 8; j++) { s1 += v[j]; s2 += v[j]*v[j]; }
    #pragma unroll
    for (int o = 16; o > 0; o >>= 1) {
        s1 += __shfl_xor_sync(0xffffffffu, s1, o);
        s2 += __shfl_xor_sync(0xffffffffu, s2, o);
    }
    float mean = s1 * (1.0f/CC);
    float var  = s2 * (1.0f/CC) - mean * mean;
    float rstd = rsqrtf(var + 1e-6f);
    const float* gp = g + lane * 8;
    const float* bp = b + lane * 8;
    float4 g0 = *(const float4*)gp, g1 = *(const float4*)(gp + 4);
    float4 b0 = *(const float4*)bp, b1 = *(const float4*)(bp + 4);
    float gg[8] = {g0.x, g0.y, g0.z, g0.w, g1.x, g1.y, g1.z, g1.w};
    float bb2[8] = {b0.x, b0.y, b0.z, b0.w, b1.x, b1.y, b1.z, b1.w};
    bf16 o8[8];
    #pragma unroll
    for (int j = 0; j < 8; j++)
        o8[j] = __float2bfloat16((v[j] - mean) * rstd * gg[j] + bb2[j]);
    *(uint4*)(out + row * CC + lane * 8) = *(uint4*)o8;
}

// ---------------- Column softmax stats (coalesced online, bf16 in) -----------
__global__ void colstat_kernel(const bf16* __restrict__ qkv,
                               float* __restrict__ cmax, float* __restrict__ csuminv) {
    int blk = blockIdx.x;
    int b = blk >> 3, cg = blk & 7;
    int t = threadIdx.x;
    int ci = t & 31, nj = t >> 5;
    const bf16* base = qkv + (size_t)b*NN*HID + CC + cg*32 + ci;
    float m = -1e30f, s = 0.f;
    for (int n = nj; n < NN; n += 8) {
        float v = __bfloat162float(base[(size_t)n*HID]);
        float mn = fmaxf(m, v);
        s = s * expf(m - mn) + expf(v - mn);
        m = mn;
    }
    __shared__ float sm[8][32], ss[8][32];
    sm[nj][ci] = m; ss[nj][ci] = s;
    __syncthreads();
    if (t < 32) {
        float M = sm[0][t], S = ss[0][t];
        #pragma unroll
        for (int j = 1; j < 8; j++) {
            float mj = sm[j][t], sj = ss[j][t];
            float mn = fmaxf(M, mj);
            S = S * expf(M - mn) + sj * expf(mj - mn);
            M = mn;
        }
        int col = b*256 + cg*32 + t;
        cmax[col] = M; csuminv[col] = 1.0f / S;
    }
}

__global__ void kv_zero_kernel(float* __restrict__ kv) {
    kv[blockIdx.x*256 + threadIdx.x] = 0.f;
}

// ---------------- kv[b,h,k,v] = sum_n softmax(k)[n,k] * v[n,v] (bf16 in) -----
__global__ __launch_bounds__(1024)
void kv_kernel(const bf16* __restrict__ qkv, const float* __restrict__ cmax,
               const float* __restrict__ csuminv, float* __restrict__ kvout) {
    int bh = blockIdx.x;
    int b = bh >> 3, hh = bh & 7;
    int t = threadIdx.x;
    int kk = t >> 5, vv = t & 31;
    int cc = t & 31;
    int r0 = t >> 5;
    __shared__ float ks[64][32];
    __shared__ float vs[64][32];
    int colbase = b*256 + hh*32;
    float mx = cmax[colbase + cc];
    float si = csuminv[colbase + cc];
    size_t nbase = (size_t)b*NN + (size_t)blockIdx.y * 1024;
    float acc = 0.f;
    for (int nt = 0; nt < 1024; nt += 64) {
        #pragma unroll
        for (int j = 0; j < 2; j++) {
            int r = r0 + j*32;
            const bf16* rowp = qkv + (nbase + nt + r)*HID + hh*32 + cc;
            ks[r][cc] = expf(__bfloat162float(rowp[CC]) - mx) * si;
            vs[r][cc] = __bfloat162float(rowp[2*CC]);
        }
        __syncthreads();
        #pragma unroll
        for (int r = 0; r < 64; r++) acc += ks[r][kk]*vs[r][vv];
        __syncthreads();
    }
    atomicAdd(&kvout[bh*1024 + kk*32 + vv], acc);
}

// ---------------- att = scale * (q@kv) + q * dwconv3x3(v), bf16 in/out -------
__global__ void att_kernel(const bf16* __restrict__ qkv, const float* __restrict__ kv,
                           const float* __restrict__ cw, const float* __restrict__ cb,
                           bf16* __restrict__ att) {
    int bn = blockIdx.x;
    int b = bn >> 14;
    int n = bn & (NN - 1);
    int y = n >> 7, x = n & 127;
    int c = threadIdx.x;
    int hh = c >> 5, dd = c & 31;
    __shared__ float qs[256];
    float qv = __bfloat162float(qkv[(size_t)bn*HID + c]);
    qs[c] = qv;
    __syncthreads();
    float f = 0.f;
    const float* kvp = kv + ((b*8 + hh) << 10) + dd;
    #pragma unroll
    for (int k = 0; k < 32; k++) f += qs[hh*32 + k] * kvp[k*32];
    float cv = cb[c];
    #pragma unroll
    for (int dy = -1; dy <= 1; dy++) {
        int yy = y + dy; if (yy < 0 || yy >= HH_IMG) continue;
        #pragma unroll
        for (int dx = -1; dx <= 1; dx++) {
            int xx = x + dx; if (xx < 0 || xx >= WW_IMG) continue;
            cv += cw[c*9 + (dy+1)*3 + (dx+1)] *
                  __bfloat162float(qkv[((size_t)b*NN + yy*WW_IMG + xx)*HID + 2*CC + c]);
        }
    }
    att[(size_t)bn*CC + c] =
        __float2bfloat16(0.17677669529663689f * f + qv * cv);
}

// ---------------- dcgelu: smem-tiled 8x8x96, gelu(hdn + dwconv3x3(hdn)) ------
#define DC_CH 96
__global__ __launch_bounds__(256)
void dcgelu_kernel(const bf16* __restrict__ hdn, const float* __restrict__ w,
                   const float* __restrict__ bias, bf16* __restrict__ out) {
    int blk = blockIdx.x;          // 8192 = 1024 tiles x 8 cgroups
    int cg = blk & 7;
    int tile = blk >> 3;
    int b = tile >> 8;
    int t16 = tile & 255;
    int ty = t16 >> 4, tx = t16 & 15;
    int y0 = ty * 8, x0 = tx * 8;
    __shared__ float sm[100 * DC_CH];      // 10x10 halo tile, ch-contig
    __shared__ float sw[DC_CH * 9];
    __shared__ float sb[DC_CH];
    int tid = threadIdx.x;
    for (int i = tid; i < DC_CH * 9; i += 256) sw[i] = w[cg * DC_CH * 9 + i];
    for (int i = tid; i < DC_CH; i += 256) sb[i] = bias[cg * DC_CH + i];
    for (int i = tid; i < 100 * DC_CH; i += 256) {
        int ch = i % DC_CH, pos = i / DC_CH;
        int yy = pos / 10, xx = pos % 10;
        int gy = y0 + yy - 1, gx = x0 + xx - 1;
        float v = 0.f;
        if (gy >= 0 && gy < HH_IMG && gx >= 0 && gx < WW_IMG)
            v = __bfloat162float(
                hdn[((size_t)b*NN + gy*WW_IMG + gx)*HID + cg*DC_CH + ch]);
        sm[i] = v;
    }
    __syncthreads();
    for (int o = tid; o < 64 * DC_CH; o += 256) {
        int ch = o % DC_CH, pos = o / DC_CH;
        int oy = pos >> 3, ox = pos & 7;
        float center = sm[((oy+1)*10 + (ox+1))*DC_CH + ch];
        float acc = sb[ch];
        #pragma unroll
        for (int dy = 0; dy < 3; dy++)
            #pragma unroll
            for (int dx = 0; dx < 3; dx++)
                acc += sw[ch*9 + dy*3 + dx] * sm[((oy+dy)*10 + (ox+dx))*DC_CH + ch];
        float ts = center + acc;
        out[((size_t)b*NN + (y0+oy)*WW_IMG + (x0+ox))*HID + cg*DC_CH + ch] =
            __float2bfloat16(0.5f * ts * (1.0f + erff(ts * 0.70710678118654752f)));
    }
}

// -----------------------------------------------------------------------------
extern "C" void kernel_launch(void* const* d_in, const int* in_sizes, int n_in,
                              void* d_out, int out_size) {
    const float* x       = (const float*)d_in[0];
    const float* ln1_g   = (const float*)d_in[3];
    const float* ln1_b   = (const float*)d_in[4];
    const float* qkv_w   = (const float*)d_in[5];
    const float* qkv_b   = (const float*)d_in[6];
    const float* crpe_w  = (const float*)d_in[7];
    const float* crpe_b  = (const float*)d_in[8];
    const float* proj_w  = (const float*)d_in[9];
    const float* proj_b  = (const float*)d_in[10];
    const float* ln2_g   = (const float*)d_in[11];
    const float* ln2_b   = (const float*)d_in[12];
    const float* fc1_w   = (const float*)d_in[13];
    const float* fc1_b   = (const float*)d_in[14];
    const float* dconv_w = (const float*)d_in[15];
    const float* dconv_b = (const float*)d_in[16];
    const float* fc2_w   = (const float*)d_in[17];
    const float* fc2_b   = (const float*)d_in[18];
    float* out = (float*)d_out;

    bf16 *p_ln, *p_qkv, *p_att, *p_hdn, *p_act;
    bf16 *p_wqkv, *p_wproj, *p_wfc1, *p_wfc2;
    float *p_x2, *p_cmax, *p_csum, *p_kv;
    cudaGetSymbolAddress((void**)&p_ln,   g_ln);
    cudaGetSymbolAddress((void**)&p_qkv,  g_qkv);
    cudaGetSymbolAddress((void**)&p_att,  g_att);
    cudaGetSymbolAddress((void**)&p_x2,   g_x2);
    cudaGetSymbolAddress((void**)&p_hdn,  g_hdn);
    cudaGetSymbolAddress((void**)&p_act,  g_act);
    cudaGetSymbolAddress((void**)&p_cmax, g_cmax);
    cudaGetSymbolAddress((void**)&p_csum, g_csuminv);
    cudaGetSymbolAddress((void**)&p_kv,   g_kv);
    cudaGetSymbolAddress((void**)&p_wqkv, g_wqkv);
    cudaGetSymbolAddress((void**)&p_wproj,g_wproj);
    cudaGetSymbolAddress((void**)&p_wfc1, g_wfc1);
    cudaGetSymbolAddress((void**)&p_wfc2, g_wfc2);

    // launch order keeps the qkv GEMM at launch index 3 (profiler slot)
    f2bf_kernel<<<(CC*HID+255)/256, 256>>>(qkv_w, p_wqkv, CC*HID);      // 0
    f2bf_kernel<<<(CC*CC +255)/256, 256>>>(proj_w, p_wproj, CC*CC);     // 1
    ln_kernel<<<MROWS/8, 256>>>(x, ln1_g, ln1_b, p_ln);                 // 2
    mma_gemm<false, bf16><<<dim3(HID/128, MROWS/128), 256>>>(           // 3 <- prof
        p_ln, p_wqkv, qkv_b, nullptr, p_qkv, MROWS, HID, CC);
    colstat_kernel<<<BB*NHEAD, 256>>>(p_qkv, p_cmax, p_csum);           // 4
    kv_zero_kernel<<<(BB*NHEAD*DHEAD*DHEAD)/256, 256>>>(p_kv);          // 5
    kv_kernel<<<dim3(BB*NHEAD, 16), 1024>>>(p_qkv, p_cmax, p_csum, p_kv); // 6
    att_kernel<<<MROWS, 256>>>(p_qkv, p_kv, crpe_w, crpe_b, p_att);     // 7
    mma_gemm<true, float><<<dim3(CC/128, MROWS/128), 256>>>(            // 8
        p_att, p_wproj, proj_b, x, p_x2, MROWS, CC, CC);

    f2bf_kernel<<<(CC*HID+255)/256, 256>>>(fc1_w, p_wfc1, CC*HID);      // 9
    ln_kernel<<<MROWS/8, 256>>>(p_x2, ln2_g, ln2_b, p_ln);              // 10
    mma_gemm<false, bf16><<<dim3(HID/128, MROWS/128), 256>>>(           // 11
        p_ln, p_wfc1, fc1_b, nullptr, p_hdn, MROWS, HID, CC);
    f2bf_kernel<<<(HID*CC+255)/256, 256>>>(fc2_w, p_wfc2, HID*CC);      // 12
    dcgelu_kernel<<<MROWS/8, 256>>>(p_hdn, dconv_w, dconv_b, p_act);    // 13
    mma_gemm<true, float><<<dim3(CC/128, MROWS/128), 256>>>(            // 14
        p_act, p_wfc2, fc2_b, p_x2, out, MROWS, CC, HID);
}